// round 17
// baseline (speedup 1.0000x reference)
#include <cuda_runtime.h>

// ComNet: R=64 runs, T=256 timesteps, N=1024 agents, MLP 4->10(tanh)->2.
// STAGGERED wavefront, skew-1, B=4, TWO ROWS PER THREAD (R16 skeleton):
// thread u owns rows (2u, 2u+1); block b = s-u of both rows per step.
//   row 2u   right-deps = row 2u-1 block b (thread u-1 @ s-1: shuffle/ring)
//   row 2u+1 right-deps = row 2u   block b (same thread, same step, registers)
// NSTEP = 447, 128 threads/CTA (1 warp/SMSP -> FFMA rt2 binds), so the MLP
// uses packed fma.rn.f32x2 (FFMA2) to halve fma-pipe occupancy. MUFU tanh.

#define R_ 64
#define T_ 256
#define N_ 1024
#define NSTEP_ 447

typedef unsigned long long ull;

__device__ __forceinline__ float htanh(float x) {
    float r; asm("tanh.approx.f32 %0, %1;" : "=f"(r) : "f"(x)); return r;
}
__device__ __forceinline__ ull pk(float lo, float hi) {
    ull r; asm("mov.b64 %0, {%1, %2};" : "=l"(r) : "f"(lo), "f"(hi)); return r;
}
__device__ __forceinline__ void upk(float& lo, float& hi, ull v) {
    asm("mov.b64 {%0, %1}, %2;" : "=f"(lo), "=f"(hi) : "l"(v));
}
__device__ __forceinline__ ull fma2(ull a, ull b, ull c) {
    ull d; asm("fma.rn.f32x2 %0, %1, %2, %3;" : "=l"(d) : "l"(a), "l"(b), "l"(c));
    return d;
}
__device__ __forceinline__ int clampN(int a) {
    return a < 0 ? 0 : (a > N_ - 1 ? N_ - 1 : a);
}

__global__ __launch_bounds__(128, 1)
void comnet_kernel(const float* __restrict__ runs,
                   const float* __restrict__ comm0,
                   const float* __restrict__ w1,
                   const float* __restrict__ b1,
                   const float* __restrict__ w2,
                   const float* __restrict__ b2,
                   float* __restrict__ out)
{
    const int r    = blockIdx.x;
    const int u    = threadIdx.x;      // owns rows 2u, 2u+1
    const int lane = u & 31;
    const int warp = u >> 5;           // 0..3

    __shared__ float4 ring[2][4];

    // ---- packed weights (pair p = hidden units 2p, 2p+1) ----
    ull W1p[20], B1p[5], W2a[5], W2b[5];
#pragma unroll
    for (int p = 0; p < 5; ++p) {
#pragma unroll
        for (int q = 0; q < 4; ++q)
            W1p[4 * p + q] = pk(w1[4 * (2 * p) + q], w1[4 * (2 * p + 1) + q]);
        B1p[p] = pk(b1[2 * p], b1[2 * p + 1]);
        W2a[p] = pk(w2[2 * p],      w2[2 * p + 1]);
        W2b[p] = pk(w2[10 + 2 * p], w2[10 + 2 * p + 1]);
    }
    const ull B2lo0 = pk(b2[0], 0.0f);
    const ull B2hi0 = pk(b2[1], 0.0f);

    const int te = 2 * u, to = 2 * u + 1;
    const float2* __restrict__ xrow_e =
        (const float2*)(runs + ((size_t)r * T_ + te) * (size_t)N_ * 2);
    const float2* __restrict__ xrow_o =
        (const float2*)(runs + ((size_t)r * T_ + to) * (size_t)N_ * 2);
    float* __restrict__ orow_e = out + ((size_t)r * T_ + te) * N_;
    float* __restrict__ orow_o = out + ((size_t)r * T_ + to) * N_;
    const float* __restrict__ c0row = comm0 + (size_t)r * N_;

    float4 h1e = make_float4(0.f, 0.f, 0.f, 0.f);  // row 2u   block @ s-1
    float4 h1o = h1e;                              // row 2u+1 block @ s-1

    // prefetch step-0 inputs: block b = -u -> A_e = -6u, A_o = -6u-1
    float2 pxe[4], pxo[4];
    float  pc[4];
#pragma unroll
    for (int k = 0; k < 4; ++k) {
        pxe[k] = xrow_e[clampN(-6 * u + k)];
        pxo[k] = xrow_o[clampN(-6 * u - 1 + k)];
    }
    if (u == 0) {
#pragma unroll
        for (int k = 0; k < 4; ++k) pc[k] = c0row[clampN(k + 1)];
    }

    // one fully-inlined cell: returns o1, stores o0 if agent valid
    #define CELL(a_, xx_, xy_, rt_, lf_, orow_, o1_)                          \
    {                                                                          \
        const float rt__ = ((a_) >= N_ - 1) ? 0.0f : (rt_);                    \
        const float lf__ = ((a_) == 0) ? 0.0f : (lf_);                         \
        const ull xx2 = pk((xx_), (xx_));                                      \
        const ull xy2 = pk((xy_), (xy_));                                      \
        const ull rt2 = pk(rt__, rt__);                                        \
        const ull lf2 = pk(lf__, lf__);                                        \
        ull A0 = B2lo0, A1 = B2hi0;                                            \
        _Pragma("unroll")                                                      \
        for (int p = 0; p < 5; ++p) {                                          \
            ull v = fma2(W1p[4 * p + 0], xx2, B1p[p]);                         \
            v     = fma2(W1p[4 * p + 1], xy2, v);                              \
            v     = fma2(W1p[4 * p + 3], rt2, v);                              \
            v     = fma2(W1p[4 * p + 2], lf2, v);                              \
            float alo, ahi; upk(alo, ahi, v);                                  \
            const ull hh = pk(htanh(alo), htanh(ahi));                         \
            A0 = fma2(W2a[p], hh, A0);                                         \
            A1 = fma2(W2b[p], hh, A1);                                         \
        }                                                                      \
        float a0l, a0h, a1l, a1h;                                              \
        upk(a0l, a0h, A0);                                                     \
        upk(a1l, a1h, A1);                                                     \
        if ((unsigned)(a_) <= (unsigned)(N_ - 1)) (orow_)[(a_)] = a0l + a0h;   \
        (o1_) = a1l + a1h;                                                     \
    }

    for (int s = 0; s < NSTEP_; ++s) {
        const int b   = s - u;
        const int Ae  = 4 * b - te;                // first agent, row 2u
        const int Ao  = Ae - 1;                    // first agent, row 2u+1
        const bool act_e = (b >= 0) && (Ae <= N_ - 1) && (Ae >= -3);
        const bool act_o = (b >= 0) && (Ao <= N_ - 1) && (Ao >= -3);

        // ---- row 2u right-deps: thread u-1's h1o (row 2u-1 block b) ----
        float r0 = __shfl_up_sync(0xffffffffu, h1o.x, 1);
        float r1 = __shfl_up_sync(0xffffffffu, h1o.y, 1);
        float r2 = __shfl_up_sync(0xffffffffu, h1o.z, 1);
        float r3 = __shfl_up_sync(0xffffffffu, h1o.w, 1);
        if (lane == 0 && warp > 0) {
            const float4 g = ring[(s + 1) & 1][warp - 1];  // written at s-1
            r0 = g.x; r1 = g.y; r2 = g.z; r3 = g.w;
        }
        if (u == 0) { r0 = pc[0]; r1 = pc[1]; r2 = pc[2]; r3 = pc[3]; }

        const float2 ex0 = pxe[0], ex1 = pxe[1], ex2 = pxe[2], ex3 = pxe[3];
        const float2 ox0 = pxo[0], ox1 = pxo[1], ox2 = pxo[2], ox3 = pxo[3];

        // ---- prefetch next step's blocks ----
        {
            const int An = Ae + 4;
#pragma unroll
            for (int k = 0; k < 4; ++k) {
                pxe[k] = xrow_e[clampN(An + k)];
                pxo[k] = xrow_o[clampN(An - 1 + k)];
            }
            if (u == 0) {
#pragma unroll
                for (int k = 0; k < 4; ++k) pc[k] = c0row[clampN(An + k + 1)];
            }
        }

        // ================= row 2u (even) =================
        float e1v[4] = {h1e.x, h1e.y, h1e.z, h1e.w};
        if (act_e) {
            float lf = h1e.w;
            CELL(Ae + 0, ex0.x, ex0.y, r0, lf, orow_e, e1v[0]); lf = e1v[0];
            CELL(Ae + 1, ex1.x, ex1.y, r1, lf, orow_e, e1v[1]); lf = e1v[1];
            CELL(Ae + 2, ex2.x, ex2.y, r2, lf, orow_e, e1v[2]); lf = e1v[2];
            CELL(Ae + 3, ex3.x, ex3.y, r3, lf, orow_e, e1v[3]);
            h1e = make_float4(e1v[0], e1v[1], e1v[2], e1v[3]);
        }

        // ========== row 2u+1 (odd): rt = row 2u same-step block ==========
        if (act_o) {
            float o1v[4];
            float lf = h1o.w;
            CELL(Ao + 0, ox0.x, ox0.y, e1v[0], lf, orow_o, o1v[0]); lf = o1v[0];
            CELL(Ao + 1, ox1.x, ox1.y, e1v[1], lf, orow_o, o1v[1]); lf = o1v[1];
            CELL(Ao + 2, ox2.x, ox2.y, e1v[2], lf, orow_o, o1v[2]); lf = o1v[2];
            CELL(Ao + 3, ox3.x, ox3.y, e1v[3], lf, orow_o, o1v[3]);
            h1o = make_float4(o1v[0], o1v[1], o1v[2], o1v[3]);
            if (lane == 31 && warp < 3) ring[s & 1][warp] = h1o;
        }

        __syncthreads();
    }
    #undef CELL
}

extern "C" void kernel_launch(void* const* d_in, const int* in_sizes, int n_in,
                              void* d_out, int out_size)
{
    const float* runs  = (const float*)d_in[0];
    const float* comm0 = (const float*)d_in[1];
    const float* w1    = (const float*)d_in[2];
    const float* b1    = (const float*)d_in[3];
    const float* w2    = (const float*)d_in[4];
    const float* b2    = (const float*)d_in[5];
    float* out = (float*)d_out;

    comnet_kernel<<<R_, 128>>>(runs, comm0, w1, b1, w2, b2, out);
}